// round 1
// baseline (speedup 1.0000x reference)
#include <cuda_runtime.h>
#include <math.h>

#define BATCH 64
#define SEQ 256
#define EMB 256
#define NHEAD 8
#define HEADD 32
#define MROWS (BATCH*SEQ)   /* 16384 */
#define ADIM 32

// ---------------- scratch (device globals; no allocation allowed) ------------
__device__ float g_x[MROWS*EMB];
__device__ float g_q[MROWS*EMB];
__device__ float g_k[MROWS*EMB];
__device__ float g_v[MROWS*EMB];
__device__ float g_g[MROWS*EMB];
__device__ float g_z[MROWS*EMB];
__device__ float g_r[MROWS*EMB];
__device__ float g_t[MROWS*EMB];

__device__ __forceinline__ float gelu_tanh(float x){
    float x3 = x*x*x;
    return 0.5f*x*(1.f + tanhf(0.7978845608028654f*(x + 0.044715f*x3)));
}
__device__ __forceinline__ float swish_f(float x){
    return x / (1.f + expf(-x));
}

// ---------------- SGEMM: C[M,N] = A[M,K] @ B[K,N], row-major -----------------
// BM=128, BN=64, BK=16, 256 threads, 8x4 per thread, double-buffered.
// EPI: 0 none, 1 gelu(acc+bias), 2 swish(acc)*aux, 3 acc+bias
template<int EPI>
__global__ __launch_bounds__(256,2)
void sgemm(const float* __restrict__ A, const float* __restrict__ B,
           float* __restrict__ C, int M, int N, int K,
           const float* __restrict__ bias, const float* __restrict__ aux)
{
    __shared__ float As[2][16][128];
    __shared__ float Bs[2][16][64];
    const int tid = threadIdx.x;
    const int bm0 = blockIdx.x * 128;
    const int bn0 = blockIdx.y * 64;
    const int ty = tid >> 4;          // 0..15 -> rows ty*8..ty*8+7
    const int tx = tid & 15;          // 0..15 -> cols tx*4..tx*4+3

    const int aRow = tid >> 1;        // 0..127
    const int aK   = (tid & 1) * 8;   // 0 or 8
    const int bK   = tid >> 4;        // 0..15
    const int bN   = (tid & 15) * 4;  // 0..60

    float acc[8][4];
    #pragma unroll
    for (int i=0;i<8;i++)
        #pragma unroll
        for (int j=0;j<4;j++) acc[i][j]=0.f;

    const int nt = K >> 4;

    // stage tile 0
    {
        const float* Ap = A + (size_t)(bm0 + aRow)*K + aK;
        float4 a0 = *(const float4*)Ap;
        float4 a1 = *(const float4*)(Ap+4);
        As[0][aK+0][aRow]=a0.x; As[0][aK+1][aRow]=a0.y;
        As[0][aK+2][aRow]=a0.z; As[0][aK+3][aRow]=a0.w;
        As[0][aK+4][aRow]=a1.x; As[0][aK+5][aRow]=a1.y;
        As[0][aK+6][aRow]=a1.z; As[0][aK+7][aRow]=a1.w;
        float4 b4 = make_float4(0.f,0.f,0.f,0.f);
        if (bn0 + bN < N) b4 = *(const float4*)(B + (size_t)bK*N + bn0 + bN);
        *(float4*)&Bs[0][bK][bN] = b4;
    }
    __syncthreads();

    for (int t=0; t<nt; t++){
        float4 pa0, pa1, pb;
        const bool more = (t+1 < nt);
        if (more){
            const float* Ap = A + (size_t)(bm0 + aRow)*K + (t+1)*16 + aK;
            pa0 = *(const float4*)Ap;
            pa1 = *(const float4*)(Ap+4);
            pb = make_float4(0.f,0.f,0.f,0.f);
            if (bn0 + bN < N) pb = *(const float4*)(B + (size_t)((t+1)*16 + bK)*N + bn0 + bN);
        }
        const int buf = t & 1;
        #pragma unroll
        for (int kk=0; kk<16; kk++){
            float4 av0 = *(const float4*)&As[buf][kk][ty*8];
            float4 av1 = *(const float4*)&As[buf][kk][ty*8+4];
            float4 bv  = *(const float4*)&Bs[buf][kk][tx*4];
            float a[8] = {av0.x,av0.y,av0.z,av0.w,av1.x,av1.y,av1.z,av1.w};
            float b[4] = {bv.x,bv.y,bv.z,bv.w};
            #pragma unroll
            for (int i=0;i<8;i++)
                #pragma unroll
                for (int j=0;j<4;j++)
                    acc[i][j] += a[i]*b[j];
        }
        if (more){
            const int nb = buf^1;
            As[nb][aK+0][aRow]=pa0.x; As[nb][aK+1][aRow]=pa0.y;
            As[nb][aK+2][aRow]=pa0.z; As[nb][aK+3][aRow]=pa0.w;
            As[nb][aK+4][aRow]=pa1.x; As[nb][aK+5][aRow]=pa1.y;
            As[nb][aK+6][aRow]=pa1.z; As[nb][aK+7][aRow]=pa1.w;
            *(float4*)&Bs[nb][bK][bN] = pb;
        }
        __syncthreads();
    }

    #pragma unroll
    for (int i=0;i<8;i++){
        const int row = bm0 + ty*8 + i;
        #pragma unroll
        for (int j=0;j<4;j++){
            const int col = bn0 + tx*4 + j;
            if (col < N){
                float vv = acc[i][j];
                if (EPI==1){ vv += (bias ? bias[col] : 0.f); vv = gelu_tanh(vv); }
                else if (EPI==2){ vv = swish_f(vv) * aux[(size_t)row*N + col]; }
                else if (EPI==3){ vv += bias[col]; }
                C[(size_t)row*N + col] = vv;
            }
        }
    }
}

// ---------------- fused retention attention ----------------------------------
// grid (S/64, NHEAD, BATCH), 256 threads. Each block: rows [rt*64, rt*64+64) of
// one (b,h). Computes scores = (q.k /sqrt(D)) * decay (causal), ret = scores@V,
// then groupnorm (per (b,s,h)) + swish gate, writes z.
__global__ __launch_bounds__(256)
void attn_kernel(const float* __restrict__ q, const float* __restrict__ k,
                 const float* __restrict__ v, const float* __restrict__ g,
                 const float* __restrict__ gns, const float* __restrict__ gnb,
                 float* __restrict__ z)
{
    __shared__ float Ks[64][36];
    __shared__ float Vs[64][36];
    __shared__ float powg[32];

    const int b = blockIdx.z, h = blockIdx.y, rt = blockIdx.x;
    const int tid = threadIdx.x;
    const int rp = tid >> 3;         // 0..31 row pair
    const int cg = tid & 7;          // col interleave group
    const int r0 = rp*2;
    const int n0 = rt*64 + r0, n1 = n0 + 1;

    if (tid < 32){
        float lg = -3.4657359027997265f + (float)h * (-0.39608410032853687f);
        float gamma = 1.f - expf(lg);
        powg[tid] = powf(gamma, (float)tid);
    }

    // Q rows -> regs, with 1/sqrt(32) folded in
    float q0[32], q1[32];
    {
        const float scale = 0.17677669529663687f;
        const float* qp0 = q + (size_t)(b*SEQ + n0)*EMB + h*HEADD;
        const float* qp1 = qp0 + EMB;
        #pragma unroll
        for (int d=0; d<32; d++){ q0[d] = qp0[d]*scale; q1[d] = qp1[d]*scale; }
    }

    float ret0[32], ret1[32];
    #pragma unroll
    for (int d=0; d<32; d++){ ret0[d]=0.f; ret1[d]=0.f; }

    const int lr = tid >> 2;          // 0..63
    const int ld = (tid & 3) * 8;     // 0,8,16,24

    for (int mc = 0; mc <= rt; mc++){
        __syncthreads();   // prev readers done (also covers powg on 1st iter)
        {
            const size_t base = (size_t)(b*SEQ + mc*64 + lr)*EMB + h*HEADD + ld;
            float4 k0 = *(const float4*)(k + base);
            float4 k1 = *(const float4*)(k + base + 4);
            float4 v0 = *(const float4*)(v + base);
            float4 v1 = *(const float4*)(v + base + 4);
            *(float4*)&Ks[lr][ld]   = k0;
            *(float4*)&Ks[lr][ld+4] = k1;
            *(float4*)&Vs[lr][ld]   = v0;
            *(float4*)&Vs[lr][ld+4] = v1;
        }
        __syncthreads();

        const bool last = (mc == rt);
        #pragma unroll
        for (int j=0;j<8;j++){
            const int ml = j*8 + cg;
            const int m  = mc*64 + ml;
            if (last && m > n1) continue;
            float s0=0.f, s1=0.f;
            #pragma unroll
            for (int d=0; d<32; d++){
                float kv = Ks[ml][d];
                s0 += q0[d]*kv;
                s1 += q1[d]*kv;
            }
            const int tm = m >> 3;
            float w0 = (m <= n0) ? powg[(n0>>3) - tm] : 0.f;
            float w1 = powg[(n1>>3) - tm];
            const float a0 = s0*w0, a1 = s1*w1;
            #pragma unroll
            for (int d=0; d<32; d++){
                float vv = Vs[ml][d];
                ret0[d] += a0*vv;
                ret1[d] += a1*vv;
            }
        }
    }

    // butterfly reduce across the 8 column groups (consecutive lanes)
    #pragma unroll
    for (int d=0; d<32; d++){
        #pragma unroll
        for (int o=1;o<8;o<<=1){
            ret0[d] += __shfl_xor_sync(0xffffffffu, ret0[d], o);
            ret1[d] += __shfl_xor_sync(0xffffffffu, ret1[d], o);
        }
    }

    // groupnorm (two-pass, per row/head) + swish gate, write 4 dims per lane/row
    float s0=0.f, s1=0.f;
    #pragma unroll
    for (int d=0; d<32; d++){ s0 += ret0[d]; s1 += ret1[d]; }
    const float mu0 = s0*(1.f/32.f), mu1 = s1*(1.f/32.f);
    float v0=0.f, v1=0.f;
    #pragma unroll
    for (int d=0; d<32; d++){
        float e0 = ret0[d]-mu0, e1 = ret1[d]-mu1;
        v0 += e0*e0; v1 += e1*e1;
    }
    const float inv0 = rsqrtf(v0*(1.f/32.f) + 1e-5f);
    const float inv1 = rsqrtf(v1*(1.f/32.f) + 1e-5f);

    const size_t base0 = (size_t)(b*SEQ + n0)*EMB + h*HEADD;
    const size_t base1 = base0 + EMB;
    #pragma unroll
    for (int jj=0; jj<4; jj++){
        const int d = cg*4 + jj;
        const float gs = gns[h*HEADD + d], gb2 = gnb[h*HEADD + d];
        float y0 = (ret0[d]-mu0)*inv0*gs + gb2;
        float y1 = (ret1[d]-mu1)*inv1*gs + gb2;
        z[base0 + d] = swish_f(g[base0 + d]) * y0;
        z[base1 + d] = swish_f(g[base1 + d]) * y1;
    }
}

// ---------------- rmsnorm (optional fused residual) --------------------------
__global__ __launch_bounds__(256)
void rmsnorm_kernel(const float* __restrict__ a, const float* __restrict__ b,
                    const float* __restrict__ scale, float* __restrict__ out)
{
    const int row = blockIdx.x;
    const int tid = threadIdx.x;
    const size_t idx = (size_t)row*EMB + tid;
    float v = a[idx];
    if (b) v += b[idx];
    float sq = v*v;
    #pragma unroll
    for (int o=16;o;o>>=1) sq += __shfl_xor_sync(0xffffffffu, sq, o);
    __shared__ float ws[8];
    if ((tid & 31) == 0) ws[tid>>5] = sq;
    __syncthreads();
    float tot = 0.f;
    #pragma unroll
    for (int w=0; w<8; w++) tot += ws[w];
    out[idx] = v * rsqrtf(tot*(1.f/256.f) + 1e-6f) * scale[tid];
}

// ---------------- launcher ---------------------------------------------------
extern "C" void kernel_launch(void* const* d_in, const int* in_sizes, int n_in,
                              void* d_out, int out_size)
{
    (void)in_sizes; (void)n_in; (void)out_size;
    const float* action = (const float*)d_in[0];
    const float* obs    = (const float*)d_in[1];
    const float* w_enc  = (const float*)d_in[2];
    const float* ln0    = (const float*)d_in[3];
    const float* wq1    = (const float*)d_in[4];
    const float* wk1    = (const float*)d_in[5];
    const float* wv1    = (const float*)d_in[6];
    const float* wg1    = (const float*)d_in[7];
    const float* wo1    = (const float*)d_in[8];
    const float* gns1   = (const float*)d_in[9];
    const float* gnb1   = (const float*)d_in[10];
    const float* ln1    = (const float*)d_in[11];
    const float* wq2    = (const float*)d_in[12];
    const float* wk2    = (const float*)d_in[13];
    const float* wv2    = (const float*)d_in[14];
    const float* wg2    = (const float*)d_in[15];
    const float* wo2    = (const float*)d_in[16];
    const float* gns2   = (const float*)d_in[17];
    const float* gnb2   = (const float*)d_in[18];
    const float* ln2    = (const float*)d_in[19];
    const float* swg    = (const float*)d_in[20];
    const float* sw1    = (const float*)d_in[21];
    const float* sw2    = (const float*)d_in[22];
    const float* ln3    = (const float*)d_in[23];
    const float* hw1    = (const float*)d_in[24];
    const float* hb1    = (const float*)d_in[25];
    const float* hln    = (const float*)d_in[26];
    const float* hw2    = (const float*)d_in[27];
    const float* hb2    = (const float*)d_in[28];
    float* out = (float*)d_out;

    float *x,*qb,*kb,*vb,*gb,*zb,*rb,*tb;
    cudaGetSymbolAddress((void**)&x,  g_x);
    cudaGetSymbolAddress((void**)&qb, g_q);
    cudaGetSymbolAddress((void**)&kb, g_k);
    cudaGetSymbolAddress((void**)&vb, g_v);
    cudaGetSymbolAddress((void**)&gb, g_g);
    cudaGetSymbolAddress((void**)&zb, g_z);
    cudaGetSymbolAddress((void**)&rb, g_r);
    cudaGetSymbolAddress((void**)&tb, g_t);

    const dim3 gFull(MROWS/128, EMB/64);     // 128 x 4
    const dim3 gHead(MROWS/128, 1);
    const dim3 gAttn(SEQ/64, NHEAD, BATCH);  // 4 x 8 x 64

    // encoder: x = rmsnorm(gelu(action @ w_enc), ln0)
    sgemm<1><<<gFull,256>>>(action, w_enc, tb, MROWS, EMB, ADIM, nullptr, nullptr);
    rmsnorm_kernel<<<MROWS,256>>>(tb, nullptr, ln0, x);

    for (int blk=0; blk<3; blk++){
        const size_t wOff = (size_t)blk*EMB*EMB;
        const size_t vOff = (size_t)blk*EMB;

        // retention 1 (self)
        sgemm<0><<<gFull,256>>>(x, wq1+wOff, qb, MROWS, EMB, EMB, nullptr, nullptr);
        sgemm<0><<<gFull,256>>>(x, wk1+wOff, kb, MROWS, EMB, EMB, nullptr, nullptr);
        sgemm<0><<<gFull,256>>>(x, wv1+wOff, vb, MROWS, EMB, EMB, nullptr, nullptr);
        sgemm<0><<<gFull,256>>>(x, wg1+wOff, gb, MROWS, EMB, EMB, nullptr, nullptr);
        attn_kernel<<<gAttn,256>>>(qb, kb, vb, gb, gns1+vOff, gnb1+vOff, zb);
        sgemm<0><<<gFull,256>>>(zb, wo1+wOff, rb, MROWS, EMB, EMB, nullptr, nullptr);
        rmsnorm_kernel<<<MROWS,256>>>(x, rb, ln1+vOff, x);

        // retention 2 (cross: q/gate from obs_rep, k/v from x)
        sgemm<0><<<gFull,256>>>(obs, wq2+wOff, qb, MROWS, EMB, EMB, nullptr, nullptr);
        sgemm<0><<<gFull,256>>>(x,   wk2+wOff, kb, MROWS, EMB, EMB, nullptr, nullptr);
        sgemm<0><<<gFull,256>>>(x,   wv2+wOff, vb, MROWS, EMB, EMB, nullptr, nullptr);
        sgemm<0><<<gFull,256>>>(obs, wg2+wOff, gb, MROWS, EMB, EMB, nullptr, nullptr);
        attn_kernel<<<gAttn,256>>>(qb, kb, vb, gb, gns2+vOff, gnb2+vOff, zb);
        sgemm<0><<<gFull,256>>>(zb, wo2+wOff, rb, MROWS, EMB, EMB, nullptr, nullptr);
        rmsnorm_kernel<<<MROWS,256>>>(obs, rb, ln2+vOff, x);

        // swiglu
        sgemm<0><<<gFull,256>>>(x, sw1+wOff, tb, MROWS, EMB, EMB, nullptr, nullptr);
        sgemm<2><<<gFull,256>>>(x, swg+wOff, zb, MROWS, EMB, EMB, nullptr, tb);
        sgemm<0><<<gFull,256>>>(zb, sw2+wOff, rb, MROWS, EMB, EMB, nullptr, nullptr);
        rmsnorm_kernel<<<MROWS,256>>>(x, rb, ln3+vOff, x);
    }

    // head
    sgemm<1><<<gFull,256>>>(x, hw1, tb, MROWS, EMB, EMB, hb1, nullptr);
    rmsnorm_kernel<<<MROWS,256>>>(tb, nullptr, hln, zb);
    sgemm<3><<<gHead,256>>>(zb, hw2, out, MROWS, ADIM, EMB, hb2, nullptr);
}

// round 6
// speedup vs baseline: 1.4896x; 1.4896x over previous
#include <cuda_runtime.h>
#include <cuda_bf16.h>
#include <math.h>
#include <stdint.h>

#define BATCH 64
#define SEQ 256
#define EMB 256
#define NHEAD 8
#define HEADD 32
#define MROWS (BATCH*SEQ)   /* 16384 */
#define ADIM 32

// ---------------- scratch (device globals; no allocation allowed) ------------
__device__ float g_x[MROWS*EMB];
__device__ float g_q[MROWS*EMB];
__device__ float g_k[MROWS*EMB];
__device__ float g_v[MROWS*EMB];
__device__ float g_g[MROWS*EMB];
__device__ float g_z[MROWS*EMB];
__device__ float g_r[MROWS*EMB];
__device__ float g_t[MROWS*EMB];

__device__ __forceinline__ float gelu_tanh(float x){
    float x3 = x*x*x;
    return 0.5f*x*(1.f + tanhf(0.7978845608028654f*(x + 0.044715f*x3)));
}
__device__ __forceinline__ float swish_f(float x){
    return x / (1.f + expf(-x));
}

__device__ __forceinline__ uint32_t smem_u32(const void* p){
    uint32_t a;
    asm("{ .reg .u64 t; cvta.to.shared.u64 t, %1; cvt.u32.u64 %0, t; }" : "=r"(a) : "l"(p));
    return a;
}

// bf16 hi/lo split of two floats, packed as bf16x2 words (memory order a,b)
__device__ __forceinline__ uint32_t pack2(float a, float b, uint32_t& lo){
    __nv_bfloat16 ha = __float2bfloat16(a), hb = __float2bfloat16(b);
    __nv_bfloat16 la = __float2bfloat16(a - __bfloat162float(ha));
    __nv_bfloat16 lb = __float2bfloat16(b - __bfloat162float(hb));
    lo = (uint32_t)__bfloat16_as_ushort(la) | ((uint32_t)__bfloat16_as_ushort(lb)<<16);
    return (uint32_t)__bfloat16_as_ushort(ha) | ((uint32_t)__bfloat16_as_ushort(hb)<<16);
}

#define LDSM4(r, addr) \
    asm volatile("ldmatrix.sync.aligned.m8n8.x4.shared.b16 {%0,%1,%2,%3}, [%4];" \
        : "=r"((r)[0]),"=r"((r)[1]),"=r"((r)[2]),"=r"((r)[3]) : "r"(addr))
#define LDSM2T(r, addr) \
    asm volatile("ldmatrix.sync.aligned.m8n8.x2.trans.shared.b16 {%0,%1}, [%2];" \
        : "=r"((r)[0]),"=r"((r)[1]) : "r"(addr))
#define MMA16816(c, a, b) \
    asm volatile("mma.sync.aligned.m16n8k16.row.col.f32.bf16.bf16.f32 " \
        "{%0,%1,%2,%3}, {%4,%5,%6,%7}, {%8,%9}, {%0,%1,%2,%3};" \
        : "+f"((c)[0]),"+f"((c)[1]),"+f"((c)[2]),"+f"((c)[3]) \
        : "r"((a)[0]),"r"((a)[1]),"r"((a)[2]),"r"((a)[3]), "r"((b)[0]),"r"((b)[1]))

// ---------------- bf16x3 HGEMM: C[M,N] = A[M,K] @ B[K,N], fp32-accurate ------
// CTA: 128(M) x 64(N), 8 warps (4x2), warp 32x32. BK=32, double-buffered smem.
// EPI: 0 none, 1 gelu(acc+bias?), 2 swish(acc)*aux, 3 acc+bias
struct GemmP {
    const float* A;
    const float* B0; const float* B1; const float* B2; const float* B3;
    float* C0; float* C1; float* C2; float* C3;
    const float* bias; const float* aux;
    int N; int K;
};

// smem per buffer (bytes): Ah 128*80=10240, Al 10240, Bh 32*144=4608, Bl 4608
#define AH_SZ 10240
#define B_SZ  4608
#define BUF_SZ (2*AH_SZ + 2*B_SZ)     /* 29696 */
#define SMEMSZ (2*BUF_SZ)             /* 59392 */

template<int EPI>
__global__ __launch_bounds__(256,2)
void hgemm(GemmP p)
{
    extern __shared__ char smem[];
    const uint32_t sb = smem_u32(smem);
    const int tid = threadIdx.x;
    const int lane = tid&31, warp = tid>>5;
    const int wm = warp&3, wn = warp>>2;
    const int bm0 = blockIdx.x*128;
    const int N = p.N, K = p.K;
    const int NT = (N>=64) ? (N>>6) : 1;
    const int mi = blockIdx.y / NT;
    const int bn0 = (blockIdx.y % NT)*64;
    const float* __restrict__ B = (mi==0)?p.B0 : (mi==1)?p.B1 : (mi==2)?p.B2 : p.B3;
    float* __restrict__ C       = (mi==0)?p.C0 : (mi==1)?p.C1 : (mi==2)?p.C2 : p.C3;
    const int nc = K>>5;

    float acc[2][4][4];
    #pragma unroll
    for (int mt=0;mt<2;mt++)
        #pragma unroll
        for (int j=0;j<4;j++)
            #pragma unroll
            for (int e=0;e<4;e++) acc[mt][j][e]=0.f;

    const int arow = tid>>1, akseg = (tid&1)*16;   // A: 128 rows x 32 k
    const int bk = tid>>3, bnn = (tid&7)*8;        // B: 32 k x 64 n

    float aR[16], bR[8];

    auto loadG = [&](int c){
        const float* Ap = p.A + (size_t)(bm0+arow)*K + c*32 + akseg;
        #pragma unroll
        for (int i=0;i<4;i++) *(float4*)(aR+4*i) = *(const float4*)(Ap + 4*i);
        if (bn0 + bnn < N){
            const float* Bp = B + (size_t)(c*32+bk)*N + bn0 + bnn;
            *(float4*)(bR)   = *(const float4*)Bp;
            *(float4*)(bR+4) = *(const float4*)(Bp+4);
        } else {
            #pragma unroll
            for (int i=0;i<8;i++) bR[i]=0.f;
        }
    };
    auto storeS = [&](int buf){
        char* ah = smem + buf*BUF_SZ + arow*80 + akseg*2;
        char* al = ah + AH_SZ;
        #pragma unroll
        for (int i=0;i<4;i++){
            uint2 hi, lo;
            hi.x = pack2(aR[4*i+0], aR[4*i+1], lo.x);
            hi.y = pack2(aR[4*i+2], aR[4*i+3], lo.y);
            *(uint2*)(ah + 8*i) = hi;
            *(uint2*)(al + 8*i) = lo;
        }
        char* bh = smem + buf*BUF_SZ + 2*AH_SZ + bk*144 + bnn*2;
        char* bl = bh + B_SZ;
        #pragma unroll
        for (int i=0;i<2;i++){
            uint2 hi, lo;
            hi.x = pack2(bR[4*i+0], bR[4*i+1], lo.x);
            hi.y = pack2(bR[4*i+2], bR[4*i+3], lo.y);
            *(uint2*)(bh + 8*i) = hi;
            *(uint2*)(bl + 8*i) = lo;
        }
    };

    loadG(0); storeS(0);
    __syncthreads();

    for (int c=0; c<nc; c++){
        const int buf = c&1;
        const bool more = (c+1 < nc);
        if (more) loadG(c+1);

        const uint32_t sA  = sb + buf*BUF_SZ;
        const uint32_t sAl = sA + AH_SZ;
        const uint32_t sB  = sA + 2*AH_SZ;
        const uint32_t sBl = sB + B_SZ;
        const uint32_t aro = (uint32_t)(wm*32 + (lane&15));
        const uint32_t bro = (uint32_t)(lane&15);

        #pragma unroll
        for (int s=0; s<2; s++){
            const uint32_t acol = (uint32_t)(s*16 + (lane>>4)*8)*2;
            uint32_t ah[2][4], al[2][4], bh[4][2], bl[4][2];
            #pragma unroll
            for (int mt=0; mt<2; mt++){
                const uint32_t ao = (aro + mt*16)*80 + acol;
                LDSM4(ah[mt], sA  + ao);
                LDSM4(al[mt], sAl + ao);
            }
            const uint32_t brow = (uint32_t)(s*16) + bro;
            #pragma unroll
            for (int j=0; j<4; j++){
                const uint32_t bo = brow*144 + (uint32_t)(wn*32 + j*8)*2;
                LDSM2T(bh[j], sB  + bo);
                LDSM2T(bl[j], sBl + bo);
            }
            #pragma unroll
            for (int mt=0; mt<2; mt++)
                #pragma unroll
                for (int j=0; j<4; j++)
                    MMA16816(acc[mt][j], ah[mt], bh[j]);
            #pragma unroll
            for (int mt=0; mt<2; mt++)
                #pragma unroll
                for (int j=0; j<4; j++)
                    MMA16816(acc[mt][j], ah[mt], bl[j]);
            #pragma unroll
            for (int mt=0; mt<2; mt++)
                #pragma unroll
                for (int j=0; j<4; j++)
                    MMA16816(acc[mt][j], al[mt], bh[j]);
        }
        if (more) storeS(buf^1);
        __syncthreads();
    }

    // epilogue: thread (mt,j): rows r0,r0+8; cols col,col+1
    const int g = lane>>2, tq = lane&3;
    #pragma unroll
    for (int mt=0; mt<2; mt++){
        const int r0 = bm0 + wm*32 + mt*16 + g;
        #pragma unroll
        for (int j=0; j<4; j++){
            const int col = bn0 + wn*32 + j*8 + tq*2;
            if (col < N){
                #pragma unroll
                for (int half=0; half<2; half++){
                    const int row = r0 + half*8;
                    float v0 = acc[mt][j][2*half+0];
                    float v1 = acc[mt][j][2*half+1];
                    if (EPI==1){
                        if (p.bias){ v0 += p.bias[col]; v1 += p.bias[col+1]; }
                        v0 = gelu_tanh(v0); v1 = gelu_tanh(v1);
                    } else if (EPI==2){
                        const float2 xa = *(const float2*)(p.aux + (size_t)row*N + col);
                        v0 = swish_f(v0)*xa.x; v1 = swish_f(v1)*xa.y;
                    } else if (EPI==3){
                        v0 += p.bias[col]; v1 += p.bias[col+1];
                    }
                    *(float2*)(C + (size_t)row*N + col) = make_float2(v0,v1);
                }
            }
        }
    }
}

// ---------------- fused retention attention ----------------------------------
__global__ __launch_bounds__(256)
void attn_kernel(const float* __restrict__ q, const float* __restrict__ k,
                 const float* __restrict__ v, const float* __restrict__ g,
                 const float* __restrict__ gns, const float* __restrict__ gnb,
                 float* __restrict__ z)
{
    __shared__ float Ks[64][36];
    __shared__ float Vs[64][36];
    __shared__ float powg[32];

    const int b = blockIdx.z, h = blockIdx.y, rt = blockIdx.x;
    const int tid = threadIdx.x;
    const int rp = tid >> 3;
    const int cg = tid & 7;
    const int r0 = rp*2;
    const int n0 = rt*64 + r0, n1 = n0 + 1;

    if (tid < 32){
        float lg = -3.4657359027997265f + (float)h * (-0.39608410032853687f);
        float gamma = 1.f - expf(lg);
        powg[tid] = powf(gamma, (float)tid);
    }

    float q0[32], q1[32];
    {
        const float scale = 0.17677669529663687f;
        const float* qp0 = q + (size_t)(b*SEQ + n0)*EMB + h*HEADD;
        const float* qp1 = qp0 + EMB;
        #pragma unroll
        for (int d=0; d<32; d++){ q0[d] = qp0[d]*scale; q1[d] = qp1[d]*scale; }
    }

    float ret0[32], ret1[32];
    #pragma unroll
    for (int d=0; d<32; d++){ ret0[d]=0.f; ret1[d]=0.f; }

    const int lr = tid >> 2;
    const int ld = (tid & 3) * 8;

    for (int mc = 0; mc <= rt; mc++){
        __syncthreads();
        {
            const size_t base = (size_t)(b*SEQ + mc*64 + lr)*EMB + h*HEADD + ld;
            float4 k0 = *(const float4*)(k + base);
            float4 k1 = *(const float4*)(k + base + 4);
            float4 v0 = *(const float4*)(v + base);
            float4 v1 = *(const float4*)(v + base + 4);
            *(float4*)&Ks[lr][ld]   = k0;
            *(float4*)&Ks[lr][ld+4] = k1;
            *(float4*)&Vs[lr][ld]   = v0;
            *(float4*)&Vs[lr][ld+4] = v1;
        }
        __syncthreads();

        const bool last = (mc == rt);
        #pragma unroll
        for (int j=0;j<8;j++){
            const int ml = j*8 + cg;
            const int m  = mc*64 + ml;
            if (last && m > n1) continue;
            float s0=0.f, s1=0.f;
            #pragma unroll
            for (int d=0; d<32; d++){
                float kv = Ks[ml][d];
                s0 += q0[d]*kv;
                s1 += q1[d]*kv;
            }
            const int tm = m >> 3;
            float w0 = (m <= n0) ? powg[(n0>>3) - tm] : 0.f;
            float w1 = powg[(n1>>3) - tm];
            const float a0 = s0*w0, a1 = s1*w1;
            #pragma unroll
            for (int d=0; d<32; d++){
                float vv = Vs[ml][d];
                ret0[d] += a0*vv;
                ret1[d] += a1*vv;
            }
        }
    }

    #pragma unroll
    for (int d=0; d<32; d++){
        #pragma unroll
        for (int o=1;o<8;o<<=1){
            ret0[d] += __shfl_xor_sync(0xffffffffu, ret0[d], o);
            ret1[d] += __shfl_xor_sync(0xffffffffu, ret1[d], o);
        }
    }

    float s0=0.f, s1=0.f;
    #pragma unroll
    for (int d=0; d<32; d++){ s0 += ret0[d]; s1 += ret1[d]; }
    const float mu0 = s0*(1.f/32.f), mu1 = s1*(1.f/32.f);
    float v0=0.f, v1=0.f;
    #pragma unroll
    for (int d=0; d<32; d++){
        float e0 = ret0[d]-mu0, e1 = ret1[d]-mu1;
        v0 += e0*e0; v1 += e1*e1;
    }
    const float inv0 = rsqrtf(v0*(1.f/32.f) + 1e-5f);
    const float inv1 = rsqrtf(v1*(1.f/32.f) + 1e-5f);

    const size_t base0 = (size_t)(b*SEQ + n0)*EMB + h*HEADD;
    const size_t base1 = base0 + EMB;
    #pragma unroll
    for (int jj=0; jj<4; jj++){
        const int d = cg*4 + jj;
        const float gs = gns[h*HEADD + d], gb2 = gnb[h*HEADD + d];
        float y0 = (ret0[d]-mu0)*inv0*gs + gb2;
        float y1 = (ret1[d]-mu1)*inv1*gs + gb2;
        z[base0 + d] = swish_f(g[base0 + d]) * y0;
        z[base1 + d] = swish_f(g[base1 + d]) * y1;
    }
}

// ---------------- rmsnorm (optional fused residual) --------------------------
__global__ __launch_bounds__(256)
void rmsnorm_kernel(const float* __restrict__ a, const float* __restrict__ b,
                    const float* __restrict__ scale, float* __restrict__ out)
{
    const int row = blockIdx.x;
    const int tid = threadIdx.x;
    const size_t idx = (size_t)row*EMB + tid;
    float v = a[idx];
    if (b) v += b[idx];
    float sq = v*v;
    #pragma unroll
    for (int o=16;o;o>>=1) sq += __shfl_xor_sync(0xffffffffu, sq, o);
    __shared__ float ws[8];
    if ((tid & 31) == 0) ws[tid>>5] = sq;
    __syncthreads();
    float tot = 0.f;
    #pragma unroll
    for (int w=0; w<8; w++) tot += ws[w];
    out[idx] = v * rsqrtf(tot*(1.f/256.f) + 1e-6f) * scale[tid];
}

// ---------------- launcher ---------------------------------------------------
static inline GemmP mkp(const float* A, const float* B0, float* C0,
                        const float* bias, const float* aux, int N, int K){
    GemmP p{}; p.A=A; p.B0=B0; p.C0=C0; p.bias=bias; p.aux=aux; p.N=N; p.K=K;
    return p;
}

extern "C" void kernel_launch(void* const* d_in, const int* in_sizes, int n_in,
                              void* d_out, int out_size)
{
    (void)in_sizes; (void)n_in; (void)out_size;
    const float* action = (const float*)d_in[0];
    const float* obs    = (const float*)d_in[1];
    const float* w_enc  = (const float*)d_in[2];
    const float* ln0    = (const float*)d_in[3];
    const float* wq1    = (const float*)d_in[4];
    const float* wk1    = (const float*)d_in[5];
    const float* wv1    = (const float*)d_in[6];
    const float* wg1    = (const float*)d_in[7];
    const float* wo1    = (const float*)d_in[8];
    const float* gns1   = (const float*)d_in[9];
    const float* gnb1   = (const float*)d_in[10];
    const float* ln1    = (const float*)d_in[11];
    const float* wq2    = (const float*)d_in[12];
    const float* wk2    = (const float*)d_in[13];
    const float* wv2    = (const float*)d_in[14];
    const float* wg2    = (const float*)d_in[15];
    const float* wo2    = (const float*)d_in[16];
    const float* gns2   = (const float*)d_in[17];
    const float* gnb2   = (const float*)d_in[18];
    const float* ln2    = (const float*)d_in[19];
    const float* swg    = (const float*)d_in[20];
    const float* sw1    = (const float*)d_in[21];
    const float* sw2    = (const float*)d_in[22];
    const float* ln3    = (const float*)d_in[23];
    const float* hw1    = (const float*)d_in[24];
    const float* hb1    = (const float*)d_in[25];
    const float* hln    = (const float*)d_in[26];
    const float* hw2    = (const float*)d_in[27];
    const float* hb2    = (const float*)d_in[28];
    float* out = (float*)d_out;

    float *x,*qb,*kb,*vb,*gb,*zb,*rb,*tb;
    cudaGetSymbolAddress((void**)&x,  g_x);
    cudaGetSymbolAddress((void**)&qb, g_q);
    cudaGetSymbolAddress((void**)&kb, g_k);
    cudaGetSymbolAddress((void**)&vb, g_v);
    cudaGetSymbolAddress((void**)&gb, g_g);
    cudaGetSymbolAddress((void**)&zb, g_z);
    cudaGetSymbolAddress((void**)&rb, g_r);
    cudaGetSymbolAddress((void**)&tb, g_t);

    cudaFuncSetAttribute(hgemm<0>, cudaFuncAttributeMaxDynamicSharedMemorySize, SMEMSZ);
    cudaFuncSetAttribute(hgemm<1>, cudaFuncAttributeMaxDynamicSharedMemorySize, SMEMSZ);
    cudaFuncSetAttribute(hgemm<2>, cudaFuncAttributeMaxDynamicSharedMemorySize, SMEMSZ);
    cudaFuncSetAttribute(hgemm<3>, cudaFuncAttributeMaxDynamicSharedMemorySize, SMEMSZ);

    const dim3 g1(MROWS/128, 4);      // one EMBxEMB gemm: 4 N-tiles
    const dim3 g2(MROWS/128, 8);      // two mats
    const dim3 g4(MROWS/128, 16);     // four mats
    const dim3 gHead(MROWS/128, 1);   // N=32
    const dim3 gAttn(SEQ/64, NHEAD, BATCH);

    // encoder: x = rmsnorm(gelu(action @ w_enc), ln0)
    hgemm<1><<<g1,256,SMEMSZ>>>(mkp(action, w_enc, tb, nullptr, nullptr, EMB, ADIM));
    rmsnorm_kernel<<<MROWS,256>>>(tb, nullptr, ln0, x);

    for (int blk=0; blk<3; blk++){
        const size_t wOff = (size_t)blk*EMB*EMB;
        const size_t vOff = (size_t)blk*EMB;

        // retention 1 (self): batched q/k/v/g projections
        {
            GemmP p{};
            p.A = x;
            p.B0 = wq1+wOff; p.B1 = wk1+wOff; p.B2 = wv1+wOff; p.B3 = wg1+wOff;
            p.C0 = qb; p.C1 = kb; p.C2 = vb; p.C3 = gb;
            p.N = EMB; p.K = EMB;
            hgemm<0><<<g4,256,SMEMSZ>>>(p);
        }
        attn_kernel<<<gAttn,256>>>(qb, kb, vb, gb, gns1+vOff, gnb1+vOff, zb);
        hgemm<0><<<g1,256,SMEMSZ>>>(mkp(zb, wo1+wOff, rb, nullptr, nullptr, EMB, EMB));
        rmsnorm_kernel<<<MROWS,256>>>(x, rb, ln1+vOff, x);

        // retention 2 (cross): k/v from x, q/g from obs_rep
        {
            GemmP p{};
            p.A = x;
            p.B0 = wk2+wOff; p.B1 = wv2+wOff;
            p.C0 = kb; p.C1 = vb;
            p.N = EMB; p.K = EMB;
            hgemm<0><<<g2,256,SMEMSZ>>>(p);
        }
        {
            GemmP p{};
            p.A = obs;
            p.B0 = wq2+wOff; p.B1 = wg2+wOff;
            p.C0 = qb; p.C1 = gb;
            p.N = EMB; p.K = EMB;
            hgemm<0><<<g2,256,SMEMSZ>>>(p);
        }
        attn_kernel<<<gAttn,256>>>(qb, kb, vb, gb, gns2+vOff, gnb2+vOff, zb);
        hgemm<0><<<g1,256,SMEMSZ>>>(mkp(zb, wo2+wOff, rb, nullptr, nullptr, EMB, EMB));
        rmsnorm_kernel<<<MROWS,256>>>(obs, rb, ln2+vOff, x);

        // swiglu
        hgemm<0><<<g1,256,SMEMSZ>>>(mkp(x, sw1+wOff, tb, nullptr, nullptr, EMB, EMB));
        hgemm<2><<<g1,256,SMEMSZ>>>(mkp(x, swg+wOff, zb, nullptr, tb, EMB, EMB));
        hgemm<0><<<g1,256,SMEMSZ>>>(mkp(zb, sw2+wOff, rb, nullptr, nullptr, EMB, EMB));
        rmsnorm_kernel<<<MROWS,256>>>(x, rb, ln3+vOff, x);
    }

    // head
    hgemm<1><<<g1,256,SMEMSZ>>>(mkp(x, hw1, tb, hb1, nullptr, EMB, EMB));
    rmsnorm_kernel<<<MROWS,256>>>(tb, nullptr, hln, zb);
    hgemm<3><<<gHead,256,SMEMSZ>>>(mkp(zb, hw2, out, hb2, nullptr, ADIM, EMB));
}

// round 7
// speedup vs baseline: 2.2298x; 1.4969x over previous
#include <cuda_runtime.h>
#include <cuda_bf16.h>
#include <math.h>
#include <stdint.h>

#define BATCH 64
#define SEQ 256
#define EMB 256
#define NHEAD 8
#define HEADD 32
#define MROWS (BATCH*SEQ)   /* 16384 */
#define ADIM 32

// ---------------- scratch (device globals; no allocation allowed) ------------
__device__ float g_x[MROWS*EMB];
__device__ float g_q[MROWS*EMB];
__device__ float g_k[MROWS*EMB];
__device__ float g_v[MROWS*EMB];
__device__ float g_g[MROWS*EMB];
__device__ float g_z[MROWS*EMB];
__device__ float g_r[MROWS*EMB];
__device__ float g_t[MROWS*EMB];

__device__ __forceinline__ float gelu_tanh(float x){
    float x3 = x*x*x;
    return 0.5f*x*(1.f + tanhf(0.7978845608028654f*(x + 0.044715f*x3)));
}
__device__ __forceinline__ float swish_f(float x){
    return x / (1.f + expf(-x));
}

__device__ __forceinline__ uint32_t smem_u32(const void* p){
    uint32_t a;
    asm("{ .reg .u64 t; cvta.to.shared.u64 t, %1; cvt.u32.u64 %0, t; }" : "=r"(a) : "l"(p));
    return a;
}

// bf16 hi/lo split of two floats, packed as bf16x2 words (memory order a,b)
__device__ __forceinline__ uint32_t pack2(float a, float b, uint32_t& lo){
    __nv_bfloat16 ha = __float2bfloat16(a), hb = __float2bfloat16(b);
    __nv_bfloat16 la = __float2bfloat16(a - __bfloat162float(ha));
    __nv_bfloat16 lb = __float2bfloat16(b - __bfloat162float(hb));
    lo = (uint32_t)__bfloat16_as_ushort(la) | ((uint32_t)__bfloat16_as_ushort(lb)<<16);
    return (uint32_t)__bfloat16_as_ushort(ha) | ((uint32_t)__bfloat16_as_ushort(hb)<<16);
}

#define LDSM4(r, addr) \
    asm volatile("ldmatrix.sync.aligned.m8n8.x4.shared.b16 {%0,%1,%2,%3}, [%4];" \
        : "=r"((r)[0]),"=r"((r)[1]),"=r"((r)[2]),"=r"((r)[3]) : "r"(addr))
#define LDSM2(r, addr) \
    asm volatile("ldmatrix.sync.aligned.m8n8.x2.shared.b16 {%0,%1}, [%2];" \
        : "=r"((r)[0]),"=r"((r)[1]) : "r"(addr))
#define LDSM2T(r, addr) \
    asm volatile("ldmatrix.sync.aligned.m8n8.x2.trans.shared.b16 {%0,%1}, [%2];" \
        : "=r"((r)[0]),"=r"((r)[1]) : "r"(addr))
#define MMA16816(c, a, b) \
    asm volatile("mma.sync.aligned.m16n8k16.row.col.f32.bf16.bf16.f32 " \
        "{%0,%1,%2,%3}, {%4,%5,%6,%7}, {%8,%9}, {%0,%1,%2,%3};" \
        : "+f"((c)[0]),"+f"((c)[1]),"+f"((c)[2]),"+f"((c)[3]) \
        : "r"((a)[0]),"r"((a)[1]),"r"((a)[2]),"r"((a)[3]), "r"((b)[0]),"r"((b)[1]))

// ---------------- bf16x3 HGEMM (unchanged, validated) ------------------------
struct GemmP {
    const float* A;
    const float* B0; const float* B1; const float* B2; const float* B3;
    float* C0; float* C1; float* C2; float* C3;
    const float* bias; const float* aux;
    int N; int K;
};

#define AH_SZ 10240
#define B_SZ  4608
#define BUF_SZ (2*AH_SZ + 2*B_SZ)
#define SMEMSZ (2*BUF_SZ)

template<int EPI>
__global__ __launch_bounds__(256,2)
void hgemm(GemmP p)
{
    extern __shared__ char smem[];
    const uint32_t sb = smem_u32(smem);
    const int tid = threadIdx.x;
    const int lane = tid&31, warp = tid>>5;
    const int wm = warp&3, wn = warp>>2;
    const int bm0 = blockIdx.x*128;
    const int N = p.N, K = p.K;
    const int NT = (N>=64) ? (N>>6) : 1;
    const int mi = blockIdx.y / NT;
    const int bn0 = (blockIdx.y % NT)*64;
    const float* __restrict__ B = (mi==0)?p.B0 : (mi==1)?p.B1 : (mi==2)?p.B2 : p.B3;
    float* __restrict__ C       = (mi==0)?p.C0 : (mi==1)?p.C1 : (mi==2)?p.C2 : p.C3;
    const int nc = K>>5;

    float acc[2][4][4];
    #pragma unroll
    for (int mt=0;mt<2;mt++)
        #pragma unroll
        for (int j=0;j<4;j++)
            #pragma unroll
            for (int e=0;e<4;e++) acc[mt][j][e]=0.f;

    const int arow = tid>>1, akseg = (tid&1)*16;
    const int bk = tid>>3, bnn = (tid&7)*8;

    float aR[16], bR[8];

    auto loadG = [&](int c){
        const float* Ap = p.A + (size_t)(bm0+arow)*K + c*32 + akseg;
        #pragma unroll
        for (int i=0;i<4;i++) *(float4*)(aR+4*i) = *(const float4*)(Ap + 4*i);
        if (bn0 + bnn < N){
            const float* Bp = B + (size_t)(c*32+bk)*N + bn0 + bnn;
            *(float4*)(bR)   = *(const float4*)Bp;
            *(float4*)(bR+4) = *(const float4*)(Bp+4);
        } else {
            #pragma unroll
            for (int i=0;i<8;i++) bR[i]=0.f;
        }
    };
    auto storeS = [&](int buf){
        char* ah = smem + buf*BUF_SZ + arow*80 + akseg*2;
        char* al = ah + AH_SZ;
        #pragma unroll
        for (int i=0;i<4;i++){
            uint2 hi, lo;
            hi.x = pack2(aR[4*i+0], aR[4*i+1], lo.x);
            hi.y = pack2(aR[4*i+2], aR[4*i+3], lo.y);
            *(uint2*)(ah + 8*i) = hi;
            *(uint2*)(al + 8*i) = lo;
        }
        char* bh = smem + buf*BUF_SZ + 2*AH_SZ + bk*144 + bnn*2;
        char* bl = bh + B_SZ;
        #pragma unroll
        for (int i=0;i<2;i++){
            uint2 hi, lo;
            hi.x = pack2(bR[4*i+0], bR[4*i+1], lo.x);
            hi.y = pack2(bR[4*i+2], bR[4*i+3], lo.y);
            *(uint2*)(bh + 8*i) = hi;
            *(uint2*)(bl + 8*i) = lo;
        }
    };

    loadG(0); storeS(0);
    __syncthreads();

    for (int c=0; c<nc; c++){
        const int buf = c&1;
        const bool more = (c+1 < nc);
        if (more) loadG(c+1);

        const uint32_t sA  = sb + buf*BUF_SZ;
        const uint32_t sAl = sA + AH_SZ;
        const uint32_t sB  = sA + 2*AH_SZ;
        const uint32_t sBl = sB + B_SZ;
        const uint32_t aro = (uint32_t)(wm*32 + (lane&15));
        const uint32_t bro = (uint32_t)(lane&15);

        #pragma unroll
        for (int s=0; s<2; s++){
            const uint32_t acol = (uint32_t)(s*16 + (lane>>4)*8)*2;
            uint32_t ah[2][4], al[2][4], bh[4][2], bl[4][2];
            #pragma unroll
            for (int mt=0; mt<2; mt++){
                const uint32_t ao = (aro + mt*16)*80 + acol;
                LDSM4(ah[mt], sA  + ao);
                LDSM4(al[mt], sAl + ao);
            }
            const uint32_t brow = (uint32_t)(s*16) + bro;
            #pragma unroll
            for (int j=0; j<4; j++){
                const uint32_t bo = brow*144 + (uint32_t)(wn*32 + j*8)*2;
                LDSM2T(bh[j], sB  + bo);
                LDSM2T(bl[j], sBl + bo);
            }
            #pragma unroll
            for (int mt=0; mt<2; mt++)
                #pragma unroll
                for (int j=0; j<4; j++)
                    MMA16816(acc[mt][j], ah[mt], bh[j]);
            #pragma unroll
            for (int mt=0; mt<2; mt++)
                #pragma unroll
                for (int j=0; j<4; j++)
                    MMA16816(acc[mt][j], ah[mt], bl[j]);
            #pragma unroll
            for (int mt=0; mt<2; mt++)
                #pragma unroll
                for (int j=0; j<4; j++)
                    MMA16816(acc[mt][j], al[mt], bh[j]);
        }
        if (more) storeS(buf^1);
        __syncthreads();
    }

    const int g = lane>>2, tq = lane&3;
    #pragma unroll
    for (int mt=0; mt<2; mt++){
        const int r0 = bm0 + wm*32 + mt*16 + g;
        #pragma unroll
        for (int j=0; j<4; j++){
            const int col = bn0 + wn*32 + j*8 + tq*2;
            if (col < N){
                #pragma unroll
                for (int half=0; half<2; half++){
                    const int row = r0 + half*8;
                    float v0 = acc[mt][j][2*half+0];
                    float v1 = acc[mt][j][2*half+1];
                    if (EPI==1){
                        if (p.bias){ v0 += p.bias[col]; v1 += p.bias[col+1]; }
                        v0 = gelu_tanh(v0); v1 = gelu_tanh(v1);
                    } else if (EPI==2){
                        const float2 xa = *(const float2*)(p.aux + (size_t)row*N + col);
                        v0 = swish_f(v0)*xa.x; v1 = swish_f(v1)*xa.y;
                    } else if (EPI==3){
                        v0 += p.bias[col]; v1 += p.bias[col+1];
                    }
                    *(float2*)(C + (size_t)row*N + col) = make_float2(v0,v1);
                }
            }
        }
    }
}

// ---------------- tensor-core retention attention ----------------------------
// decay factorized: w[n,m] = gamma^(t_n) * gamma^(-t_m), causal mask at element
// level. Q rows scaled by gamma^(t_n)/sqrt(D), K rows by gamma^(-t_m). Then:
//   S = Qs @ Ks^T  (masked)  ;  O = S @ V   — both bf16x3 MMA chains.
// Grid (SEQ/128, NHEAD, BATCH), 256 thr. Warp w owns rows wid*16..+15.
// Fused groupnorm + swish(gate) epilogue.
#define QROW 80
__global__ __launch_bounds__(256,2)
void attn_tc(const float* __restrict__ q, const float* __restrict__ k,
             const float* __restrict__ v, const float* __restrict__ g,
             const float* __restrict__ gns, const float* __restrict__ gnb,
             float* __restrict__ z)
{
    __shared__ __align__(16) char sQh[128*QROW];
    __shared__ __align__(16) char sQl[128*QROW];
    __shared__ __align__(16) char sKh[64*QROW];
    __shared__ __align__(16) char sKl[64*QROW];
    __shared__ __align__(16) char sVh[64*QROW];
    __shared__ __align__(16) char sVl[64*QROW];
    __shared__ float pg[32], pgi[32];

    const int b = blockIdx.z, h = blockIdx.y, rt = blockIdx.x;
    const int tid = threadIdx.x;
    const int lane = tid&31, wid = tid>>5;

    if (tid < 32){
        float lg = -3.4657359027997265f + (float)h * (-0.39608410032853687f);
        float gamma = 1.f - expf(lg);
        pg[tid]  = powf(gamma, (float)tid) * 0.17677669529663687f; // gamma^t / sqrt(32)
        pgi[tid] = powf(gamma, -(float)tid);                        // gamma^-t
    }
    __syncthreads();

    // load Q (128 rows x 32 d), scaled, split hi/lo
    {
        const int row = tid>>1, seg = (tid&1)*16;
        const int n = rt*128 + row;
        const float qs = pg[n>>3];
        const float* Qp = q + (size_t)(b*SEQ + n)*EMB + h*HEADD + seg;
        char* qh = sQh + row*QROW + seg*2;
        char* ql = sQl + row*QROW + seg*2;
        #pragma unroll
        for (int i=0;i<4;i++){
            float4 x4 = *(const float4*)(Qp + 4*i);
            uint2 hi, lo;
            hi.x = pack2(x4.x*qs, x4.y*qs, lo.x);
            hi.y = pack2(x4.z*qs, x4.w*qs, lo.y);
            *(uint2*)(qh + 8*i) = hi;
            *(uint2*)(ql + 8*i) = lo;
        }
    }
    __syncthreads();

    // persistent Q fragments for this warp (16 rows x 32 k)
    uint32_t qfh[2][4], qfl[2][4];
    {
        const uint32_t qb = smem_u32(sQh), qlb = smem_u32(sQl);
        const uint32_t aro = (uint32_t)(wid*16 + (lane&15));
        #pragma unroll
        for (int kt=0; kt<2; kt++){
            const uint32_t ao = aro*QROW + (uint32_t)(kt*16 + (lane>>4)*8)*2;
            LDSM4(qfh[kt], qb + ao);
            LDSM4(qfl[kt], qlb + ao);
        }
    }

    float oacc[4][4];
    #pragma unroll
    for (int jn=0;jn<4;jn++)
        #pragma unroll
        for (int e=0;e<4;e++) oacc[jn][e]=0.f;

    const int rowbase = rt*128 + wid*16;
    const int nchunks = 2*(rt+1);

    const uint32_t kb  = smem_u32(sKh), klb = smem_u32(sKl);
    const uint32_t vb  = smem_u32(sVh), vlb = smem_u32(sVl);

    for (int mc=0; mc<nchunks; mc++){
        __syncthreads();
        // load K/V chunk (64 rows x 32 d), K scaled by gamma^-t
        {
            const int row = tid>>2, seg = (tid&3)*8;
            const int m = mc*64 + row;
            const float ks = pgi[m>>3];
            const size_t base = (size_t)(b*SEQ + m)*EMB + h*HEADD + seg;
            float4 k0 = *(const float4*)(k + base);
            float4 k1 = *(const float4*)(k + base + 4);
            float4 v0 = *(const float4*)(v + base);
            float4 v1 = *(const float4*)(v + base + 4);
            char* kh = sKh + row*QROW + seg*2;
            char* kl = sKl + row*QROW + seg*2;
            char* vh = sVh + row*QROW + seg*2;
            char* vl = sVl + row*QROW + seg*2;
            uint2 hi, lo;
            hi.x = pack2(k0.x*ks, k0.y*ks, lo.x);
            hi.y = pack2(k0.z*ks, k0.w*ks, lo.y);
            *(uint2*)kh = hi; *(uint2*)kl = lo;
            hi.x = pack2(k1.x*ks, k1.y*ks, lo.x);
            hi.y = pack2(k1.z*ks, k1.w*ks, lo.y);
            *(uint2*)(kh+8) = hi; *(uint2*)(kl+8) = lo;
            hi.x = pack2(v0.x, v0.y, lo.x);
            hi.y = pack2(v0.z, v0.w, lo.y);
            *(uint2*)vh = hi; *(uint2*)vl = lo;
            hi.x = pack2(v1.x, v1.y, lo.x);
            hi.y = pack2(v1.z, v1.w, lo.y);
            *(uint2*)(vh+8) = hi; *(uint2*)(vl+8) = lo;
        }
        __syncthreads();

        const int mbase = mc*64;
        if (mbase > rowbase + 15) continue;   // fully masked for this warp

        // ---- S = Qs @ Ks^T : 16 x 64 ----
        float sacc[8][4];
        #pragma unroll
        for (int j=0;j<8;j++)
            #pragma unroll
            for (int e=0;e<4;e++) sacc[j][e]=0.f;

        #pragma unroll
        for (int kt=0; kt<2; kt++){
            #pragma unroll
            for (int j=0; j<8; j++){
                const uint32_t addr = (uint32_t)(j*8 + (lane&7))*QROW
                                    + (uint32_t)((lane>>3)&1)*16 + (uint32_t)kt*32;
                uint32_t kfh[2], kfl[2];
                LDSM2(kfh, kb  + addr);
                LDSM2(kfl, klb + addr);
                MMA16816(sacc[j], qfh[kt], kfh);
                MMA16816(sacc[j], qfl[kt], kfh);
                MMA16816(sacc[j], qfh[kt], kfl);
            }
        }

        // causal mask (m > n -> 0)
        if (mbase + 63 > rowbase){
            const int nr = rowbase + (lane>>2);
            const int mcb = mbase + (lane&3)*2;
            #pragma unroll
            for (int j=0;j<8;j++){
                const int m0 = mcb + j*8;
                if (m0   > nr)   sacc[j][0]=0.f;
                if (m0+1 > nr)   sacc[j][1]=0.f;
                if (m0   > nr+8) sacc[j][2]=0.f;
                if (m0+1 > nr+8) sacc[j][3]=0.f;
            }
        }

        // ---- O += S @ V : k=64 over 4 k16-steps ----
        #pragma unroll
        for (int kt2=0; kt2<4; kt2++){
            uint32_t ah[4], al[4];
            ah[0] = pack2(sacc[2*kt2][0],   sacc[2*kt2][1],   al[0]);
            ah[1] = pack2(sacc[2*kt2][2],   sacc[2*kt2][3],   al[1]);
            ah[2] = pack2(sacc[2*kt2+1][0], sacc[2*kt2+1][1], al[2]);
            ah[3] = pack2(sacc[2*kt2+1][2], sacc[2*kt2+1][3], al[3]);
            #pragma unroll
            for (int jn=0; jn<4; jn++){
                const uint32_t addr = (uint32_t)(kt2*16 + (lane&15))*QROW
                                    + (uint32_t)(jn*8)*2;
                uint32_t vfh[2], vfl[2];
                LDSM2T(vfh, vb  + addr);
                LDSM2T(vfl, vlb + addr);
                MMA16816(oacc[jn], ah, vfh);
                MMA16816(oacc[jn], al, vfh);
                MMA16816(oacc[jn], ah, vfl);
            }
        }
    }

    // ---- epilogue: groupnorm over 32 dims + swish gate ----
    const int gl = lane>>2, tq = lane&3;
    float sum0=0.f, sum1=0.f;
    #pragma unroll
    for (int jn=0;jn<4;jn++){
        sum0 += oacc[jn][0] + oacc[jn][1];
        sum1 += oacc[jn][2] + oacc[jn][3];
    }
    sum0 += __shfl_xor_sync(0xffffffffu, sum0, 1);
    sum0 += __shfl_xor_sync(0xffffffffu, sum0, 2);
    sum1 += __shfl_xor_sync(0xffffffffu, sum1, 1);
    sum1 += __shfl_xor_sync(0xffffffffu, sum1, 2);
    const float mu0 = sum0*(1.f/32.f), mu1 = sum1*(1.f/32.f);
    float v0=0.f, v1=0.f;
    #pragma unroll
    for (int jn=0;jn<4;jn++){
        float d0 = oacc[jn][0]-mu0, d1 = oacc[jn][1]-mu0;
        float d2 = oacc[jn][2]-mu1, d3 = oacc[jn][3]-mu1;
        v0 += d0*d0 + d1*d1;
        v1 += d2*d2 + d3*d3;
    }
    v0 += __shfl_xor_sync(0xffffffffu, v0, 1);
    v0 += __shfl_xor_sync(0xffffffffu, v0, 2);
    v1 += __shfl_xor_sync(0xffffffffu, v1, 1);
    v1 += __shfl_xor_sync(0xffffffffu, v1, 2);
    const float inv0 = rsqrtf(v0*(1.f/32.f) + 1e-5f);
    const float inv1 = rsqrtf(v1*(1.f/32.f) + 1e-5f);

    const int n0 = rowbase + gl;
    const size_t base0 = (size_t)(b*SEQ + n0)*EMB + h*HEADD;
    const size_t base1 = base0 + 8*EMB;
    #pragma unroll
    for (int jn=0;jn<4;jn++){
        const int c = jn*8 + tq*2;
        const float2 gs = *(const float2*)(gns + h*HEADD + c);
        const float2 gb2 = *(const float2*)(gnb + h*HEADD + c);
        float2 gg0 = *(const float2*)(g + base0 + c);
        float2 gg1 = *(const float2*)(g + base1 + c);
        float y0 = (oacc[jn][0]-mu0)*inv0*gs.x + gb2.x;
        float y1 = (oacc[jn][1]-mu0)*inv0*gs.y + gb2.y;
        float y2 = (oacc[jn][2]-mu1)*inv1*gs.x + gb2.x;
        float y3 = (oacc[jn][3]-mu1)*inv1*gs.y + gb2.y;
        *(float2*)(z + base0 + c) = make_float2(swish_f(gg0.x)*y0, swish_f(gg0.y)*y1);
        *(float2*)(z + base1 + c) = make_float2(swish_f(gg1.x)*y2, swish_f(gg1.y)*y3);
    }
}

// ---------------- rmsnorm (optional fused residual) --------------------------
__global__ __launch_bounds__(256)
void rmsnorm_kernel(const float* __restrict__ a, const float* __restrict__ b,
                    const float* __restrict__ scale, float* __restrict__ out)
{
    const int row = blockIdx.x;
    const int tid = threadIdx.x;
    const size_t idx = (size_t)row*EMB + tid;
    float v = a[idx];
    if (b) v += b[idx];
    float sq = v*v;
    #pragma unroll
    for (int o=16;o;o>>=1) sq += __shfl_xor_sync(0xffffffffu, sq, o);
    __shared__ float ws[8];
    if ((tid & 31) == 0) ws[tid>>5] = sq;
    __syncthreads();
    float tot = 0.f;
    #pragma unroll
    for (int w=0; w<8; w++) tot += ws[w];
    out[idx] = v * rsqrtf(tot*(1.f/256.f) + 1e-6f) * scale[tid];
}

// ---------------- launcher ---------------------------------------------------
static inline GemmP mkp(const float* A, const float* B0, float* C0,
                        const float* bias, const float* aux, int N, int K){
    GemmP p{}; p.A=A; p.B0=B0; p.C0=C0; p.bias=bias; p.aux=aux; p.N=N; p.K=K;
    return p;
}

extern "C" void kernel_launch(void* const* d_in, const int* in_sizes, int n_in,
                              void* d_out, int out_size)
{
    (void)in_sizes; (void)n_in; (void)out_size;
    const float* action = (const float*)d_in[0];
    const float* obs    = (const float*)d_in[1];
    const float* w_enc  = (const float*)d_in[2];
    const float* ln0    = (const float*)d_in[3];
    const float* wq1    = (const float*)d_in[4];
    const float* wk1    = (const float*)d_in[5];
    const float* wv1    = (const float*)d_in[6];
    const float* wg1    = (const float*)d_in[7];
    const float* wo1    = (const float*)d_in[8];
    const float* gns1   = (const float*)d_in[9];
    const float* gnb1   = (const float*)d_in[10];
    const float* ln1    = (const float*)d_in[11];
    const float* wq2    = (const float*)d_in[12];
    const float* wk2    = (const float*)d_in[13];
    const float* wv2    = (const float*)d_in[14];
    const float* wg2    = (const float*)d_in[15];
    const float* wo2    = (const float*)d_in[16];
    const float* gns2   = (const float*)d_in[17];
    const float* gnb2   = (const float*)d_in[18];
    const float* ln2    = (const float*)d_in[19];
    const float* swg    = (const float*)d_in[20];
    const float* sw1    = (const float*)d_in[21];
    const float* sw2    = (const float*)d_in[22];
    const float* ln3    = (const float*)d_in[23];
    const float* hw1    = (const float*)d_in[24];
    const float* hb1    = (const float*)d_in[25];
    const float* hln    = (const float*)d_in[26];
    const float* hw2    = (const float*)d_in[27];
    const float* hb2    = (const float*)d_in[28];
    float* out = (float*)d_out;

    float *x,*qb,*kb,*vb,*gb,*zb,*rb,*tb;
    cudaGetSymbolAddress((void**)&x,  g_x);
    cudaGetSymbolAddress((void**)&qb, g_q);
    cudaGetSymbolAddress((void**)&kb, g_k);
    cudaGetSymbolAddress((void**)&vb, g_v);
    cudaGetSymbolAddress((void**)&gb, g_g);
    cudaGetSymbolAddress((void**)&zb, g_z);
    cudaGetSymbolAddress((void**)&rb, g_r);
    cudaGetSymbolAddress((void**)&tb, g_t);

    cudaFuncSetAttribute(hgemm<0>, cudaFuncAttributeMaxDynamicSharedMemorySize, SMEMSZ);
    cudaFuncSetAttribute(hgemm<1>, cudaFuncAttributeMaxDynamicSharedMemorySize, SMEMSZ);
    cudaFuncSetAttribute(hgemm<2>, cudaFuncAttributeMaxDynamicSharedMemorySize, SMEMSZ);
    cudaFuncSetAttribute(hgemm<3>, cudaFuncAttributeMaxDynamicSharedMemorySize, SMEMSZ);

    const dim3 g1(MROWS/128, 4);
    const dim3 g2(MROWS/128, 8);
    const dim3 g4(MROWS/128, 16);
    const dim3 gHead(MROWS/128, 1);
    const dim3 gAttn(SEQ/128, NHEAD, BATCH);   // 2 x 8 x 64 = 1024 CTAs

    // encoder: x = rmsnorm(gelu(action @ w_enc), ln0)
    hgemm<1><<<g1,256,SMEMSZ>>>(mkp(action, w_enc, tb, nullptr, nullptr, EMB, ADIM));
    rmsnorm_kernel<<<MROWS,256>>>(tb, nullptr, ln0, x);

    for (int blk=0; blk<3; blk++){
        const size_t wOff = (size_t)blk*EMB*EMB;
        const size_t vOff = (size_t)blk*EMB;

        // retention 1 (self): batched q/k/v/g projections
        {
            GemmP p{};
            p.A = x;
            p.B0 = wq1+wOff; p.B1 = wk1+wOff; p.B2 = wv1+wOff; p.B3 = wg1+wOff;
            p.C0 = qb; p.C1 = kb; p.C2 = vb; p.C3 = gb;
            p.N = EMB; p.K = EMB;
            hgemm<0><<<g4,256,SMEMSZ>>>(p);
        }
        attn_tc<<<gAttn,256>>>(qb, kb, vb, gb, gns1+vOff, gnb1+vOff, zb);
        hgemm<0><<<g1,256,SMEMSZ>>>(mkp(zb, wo1+wOff, rb, nullptr, nullptr, EMB, EMB));
        rmsnorm_kernel<<<MROWS,256>>>(x, rb, ln1+vOff, x);

        // retention 2 (cross): k/v from x, q/g from obs_rep
        {
            GemmP p{};
            p.A = x;
            p.B0 = wk2+wOff; p.B1 = wv2+wOff;
            p.C0 = kb; p.C1 = vb;
            p.N = EMB; p.K = EMB;
            hgemm<0><<<g2,256,SMEMSZ>>>(p);
        }
        {
            GemmP p{};
            p.A = obs;
            p.B0 = wq2+wOff; p.B1 = wg2+wOff;
            p.C0 = qb; p.C1 = gb;
            p.N = EMB; p.K = EMB;
            hgemm<0><<<g2,256,SMEMSZ>>>(p);
        }
        attn_tc<<<gAttn,256>>>(qb, kb, vb, gb, gns2+vOff, gnb2+vOff, zb);
        hgemm<0><<<g1,256,SMEMSZ>>>(mkp(zb, wo2+wOff, rb, nullptr, nullptr, EMB, EMB));
        rmsnorm_kernel<<<MROWS,256>>>(obs, rb, ln2+vOff, x);

        // swiglu
        hgemm<0><<<g1,256,SMEMSZ>>>(mkp(x, sw1+wOff, tb, nullptr, nullptr, EMB, EMB));
        hgemm<2><<<g1,256,SMEMSZ>>>(mkp(x, swg+wOff, zb, nullptr, tb, EMB, EMB));
        hgemm<0><<<g1,256,SMEMSZ>>>(mkp(zb, sw2+wOff, rb, nullptr, nullptr, EMB, EMB));
        rmsnorm_kernel<<<MROWS,256>>>(x, rb, ln3+vOff, x);
    }

    // head
    hgemm<1><<<g1,256,SMEMSZ>>>(mkp(x, hw1, tb, hb1, nullptr, EMB, EMB));
    rmsnorm_kernel<<<MROWS,256>>>(tb, nullptr, hln, zb);
    hgemm<3><<<gHead,256,SMEMSZ>>>(mkp(zb, hw2, out, hb2, nullptr, ADIM, EMB));
}